// round 4
// baseline (speedup 1.0000x reference)
#include <cuda_runtime.h>

#define BB  8
#define CC  256
#define PP  64
#define HH  64
#define WW  64
#define HWS 4096   // H*W

// ---------------- scratch (device globals; no allocations allowed) ----------
__device__ __align__(128) float g_top[BB * PP * HWS];        // [B][P][HW]
__device__ __align__(128) float g_centerT[BB * HWS * PP];    // [B][HW][P]
__device__ __align__(128) float g_bottom[BB * HWS * CC];     // [B][HW][C]
__device__ __align__(128) float g_S[134217728];              // [B][HW][HW] 536MB
__device__ __align__(128) float g_attn[BB * HWS * CC];       // [B][HW][C] == reinterpret [B][C][H][W]
__device__ float g_partial[BB * 2048];
__device__ float g_sum[BB];

// ---------------- packed f32x2 helpers (FFMA2 path) -------------------------
typedef unsigned long long u64;

__device__ __forceinline__ u64 bcast2(float v) {
    u64 r;
    asm("mov.b64 %0, {%1, %1};" : "=l"(r) : "f"(v));
    return r;
}
__device__ __forceinline__ void ffma2(u64 &d, u64 a, u64 b) {
    asm("fma.rn.f32x2 %0, %1, %2, %0;" : "+l"(d) : "l"(a), "l"(b));
}
__device__ __forceinline__ float2 unpack2(u64 v) {
    float2 f;
    asm("mov.b64 {%0, %1}, %2;" : "=f"(f.x), "=f"(f.y) : "l"(v));
    return f;
}

// 8x8 microkernel update with packed accumulators acc2[i][jp] = (j=2*jp, 2*jp+1)
__device__ __forceinline__ void mk_update(u64 acc2[8][4],
                                          const float* Asrow,
                                          const float* Bsrow)
{
    float a[8];
    *(float4*)(a)     = *(const float4*)(Asrow);
    *(float4*)(a + 4) = *(const float4*)(Asrow + 4);
    u64 b2[4];
    {
        ulonglong2 t0 = *(const ulonglong2*)(Bsrow);
        ulonglong2 t1 = *(const ulonglong2*)(Bsrow + 4);
        b2[0] = t0.x; b2[1] = t0.y; b2[2] = t1.x; b2[3] = t1.y;
    }
#pragma unroll
    for (int i = 0; i < 8; i++) {
        u64 a2 = bcast2(a[i]);
#pragma unroll
        for (int jp = 0; jp < 4; jp++) ffma2(acc2[i][jp], a2, b2[jp]);
    }
}

// ---------------- K1: 1x1 convs (top + centerT fused) -----------------------
__global__ void k_top_center(const float* __restrict__ x,
                             const float* __restrict__ wt, const float* __restrict__ bt,
                             const float* __restrict__ wc, const float* __restrict__ bc)
{
    const int b  = blockIdx.y;
    const int n0 = blockIdx.x * 64;
    const int t  = threadIdx.x;
    const int p  = t & 63;
    const int q  = t >> 6;         // 0..3, 16 n's each

    __shared__ float xs[16][64];
    __shared__ float wts[64][17];
    __shared__ float wcs[64][17];

    float acct[16], accc[16];
#pragma unroll
    for (int j = 0; j < 16; j++) { acct[j] = 0.f; accc[j] = 0.f; }

    const float* xb = x + (size_t)b * CC * HWS;

    for (int c0 = 0; c0 < CC; c0 += 16) {
        {
            int cc = t >> 4;
            int nn = (t & 15) * 4;
            float4 v = *(const float4*)(xb + (size_t)(c0 + cc) * HWS + n0 + nn);
            *(float4*)&xs[cc][nn] = v;
        }
        {
            int p_ = t >> 2;
            int cq = (t & 3) * 4;
            float4 v = *(const float4*)(wt + (size_t)p_ * CC + c0 + cq);
            wts[p_][cq + 0] = v.x; wts[p_][cq + 1] = v.y; wts[p_][cq + 2] = v.z; wts[p_][cq + 3] = v.w;
            float4 u = *(const float4*)(wc + (size_t)p_ * CC + c0 + cq);
            wcs[p_][cq + 0] = u.x; wcs[p_][cq + 1] = u.y; wcs[p_][cq + 2] = u.z; wcs[p_][cq + 3] = u.w;
        }
        __syncthreads();
#pragma unroll
        for (int cc = 0; cc < 16; cc++) {
            float at = wts[p][cc];
            float ac = wcs[p][cc];
#pragma unroll
            for (int j = 0; j < 16; j++) {
                float xv = xs[cc][q * 16 + j];
                acct[j] += at * xv;
                accc[j] += ac * xv;
            }
        }
        __syncthreads();
    }

    const float btv = bt[p];
    const float bcv = bc[p];
    float* topp = g_top + ((size_t)b * PP + p) * HWS + n0 + q * 16;
#pragma unroll
    for (int j4 = 0; j4 < 4; j4++) {
        float4 v = make_float4(acct[j4*4+0] + btv, acct[j4*4+1] + btv,
                               acct[j4*4+2] + btv, acct[j4*4+3] + btv);
        *(float4*)(topp + j4 * 4) = v;
    }
    float* cenp = g_centerT + (size_t)b * HWS * PP + (size_t)(n0 + q * 16) * PP + p;
#pragma unroll
    for (int j = 0; j < 16; j++) cenp[(size_t)j * PP] = accc[j] + bcv;
}

// ---------------- K2: 3x3 conv -> bottomT [B][HW][C]  (implicit GEMM) -------
__global__ void k_conv_bottom(const float* __restrict__ x,
                              const float* __restrict__ w, const float* __restrict__ bias)
{
    const int b  = blockIdx.z;
    const int n0 = blockIdx.x * 128;
    const int m0 = blockIdx.y * 128;
    const int t  = threadIdx.x;
    const int tx = t & 15, ty = t >> 4;

    __shared__ float As[8][128];
    __shared__ float Bs[8][128];

    u64 acc2[8][4];
#pragma unroll
    for (int i = 0; i < 8; i++)
#pragma unroll
        for (int j = 0; j < 4; j++) acc2[i][j] = 0ULL;

    const float* xb = x + (size_t)b * CC * HWS;

    for (int k0 = 0; k0 < 2304; k0 += 8) {
        {
            int m  = t >> 1;
            int kq = (t & 1) * 4;
            float4 v = *(const float4*)(w + (size_t)(m0 + m) * 2304 + k0 + kq);
            As[kq + 0][m] = v.x; As[kq + 1][m] = v.y; As[kq + 2][m] = v.z; As[kq + 3][m] = v.w;
        }
        {
            int kb   = t >> 5;
            int kidx = k0 + kb;
            int ci   = kidx / 9;
            int r    = kidx - ci * 9;
            int dh   = r / 3 - 1;
            int dw   = r - (r / 3) * 3 - 1;
            const float* src = xb + (size_t)ci * HWS;
            int lane = t & 31;
#pragma unroll
            for (int it = 0; it < 4; it++) {
                int n  = n0 + lane + 32 * it;
                int h  = n >> 6, wc_ = n & 63;
                int hh = h + dh, ww = wc_ + dw;
                float v = 0.f;
                if ((unsigned)hh < 64u && (unsigned)ww < 64u) v = src[hh * 64 + ww];
                Bs[kb][lane + 32 * it] = v;
            }
        }
        __syncthreads();
#pragma unroll
        for (int kk = 0; kk < 8; kk++)
            mk_update(acc2, &As[kk][ty * 8], &Bs[kk][tx * 8]);
        __syncthreads();
    }

    float bcol[8];
#pragma unroll
    for (int i = 0; i < 8; i++) bcol[i] = bias[m0 + ty * 8 + i];

    float* outp = g_bottom + (size_t)b * HWS * CC;
    float accf[8][8];
#pragma unroll
    for (int i = 0; i < 8; i++)
#pragma unroll
        for (int jp = 0; jp < 4; jp++) {
            float2 f = unpack2(acc2[i][jp]);
            accf[i][jp * 2] = f.x; accf[i][jp * 2 + 1] = f.y;
        }
#pragma unroll
    for (int j = 0; j < 8; j++) {
        int n = n0 + tx * 8 + j;
        float4 v0 = make_float4(accf[0][j] + bcol[0], accf[1][j] + bcol[1],
                                accf[2][j] + bcol[2], accf[3][j] + bcol[3]);
        float4 v1 = make_float4(accf[4][j] + bcol[4], accf[5][j] + bcol[5],
                                accf[6][j] + bcol[6], accf[7][j] + bcol[7]);
        *(float4*)(outp + (size_t)n * CC + m0 + ty * 8)     = v0;
        *(float4*)(outp + (size_t)n * CC + m0 + ty * 8 + 4) = v1;
    }
}

// ---------------- K3: S = centerT(4096x64) @ top(64x4096) -------------------
__global__ void k_gemm_S()
{
    const int b  = blockIdx.z;
    const int n0 = blockIdx.x * 128;
    const int m0 = blockIdx.y * 128;
    const int t  = threadIdx.x;
    const int tx = t & 15, ty = t >> 4;

    const float* A  = g_centerT + (size_t)b * HWS * PP + (size_t)m0 * PP;
    const float* Bm = g_top + (size_t)b * PP * HWS + n0;
    float*       Sb = g_S + (size_t)b * HWS * HWS;

    __shared__ float As[8][128];
    __shared__ float Bs[8][128];

    u64 acc2[8][4];
#pragma unroll
    for (int i = 0; i < 8; i++)
#pragma unroll
        for (int j = 0; j < 4; j++) acc2[i][j] = 0ULL;

    for (int k0 = 0; k0 < PP; k0 += 8) {
        {
            int m  = t >> 1;
            int kq = (t & 1) * 4;
            float4 v = *(const float4*)(A + (size_t)m * PP + k0 + kq);
            As[kq + 0][m] = v.x; As[kq + 1][m] = v.y; As[kq + 2][m] = v.z; As[kq + 3][m] = v.w;
        }
        {
            int kb = t >> 5;
            int nb = (t & 31) * 4;
            *(float4*)&Bs[kb][nb] = *(const float4*)(Bm + (size_t)(k0 + kb) * HWS + nb);
        }
        __syncthreads();
#pragma unroll
        for (int kk = 0; kk < 8; kk++)
            mk_update(acc2, &As[kk][ty * 8], &Bs[kk][tx * 8]);
        __syncthreads();
    }

#pragma unroll
    for (int i = 0; i < 8; i++) {
        float2 f0 = unpack2(acc2[i][0]);
        float2 f1 = unpack2(acc2[i][1]);
        float2 f2 = unpack2(acc2[i][2]);
        float2 f3 = unpack2(acc2[i][3]);
        float* row = Sb + (size_t)(m0 + ty * 8 + i) * HWS + n0 + tx * 8;
        *(float4*)(row)     = make_float4(f0.x, f0.y, f1.x, f1.y);
        *(float4*)(row + 4) = make_float4(f2.x, f2.y, f3.x, f3.y);
    }
}

// ---------------- K4: per-batch sum of exp(S - 40) (deterministic) ----------
__global__ void k_expsum()
{
    const int b   = blockIdx.y;
    const int tid = threadIdx.x;
    size_t base = (size_t)b * HWS * HWS + (size_t)blockIdx.x * 8192 + tid;
    float s = 0.f;
#pragma unroll
    for (int it = 0; it < 32; it++)
        s += __expf(g_S[base + (size_t)it * 256] - 40.f);

    __shared__ float red[256];
    red[tid] = s;
    __syncthreads();
    for (int st = 128; st > 0; st >>= 1) {
        if (tid < st) red[tid] += red[tid + st];
        __syncthreads();
    }
    if (tid == 0) g_partial[b * 2048 + blockIdx.x] = red[0];
}

__global__ void k_expsum2()
{
    const int b   = blockIdx.x;
    const int tid = threadIdx.x;
    float s = 0.f;
    for (int i = tid; i < 2048; i += 256) s += g_partial[b * 2048 + i];
    __shared__ float red[256];
    red[tid] = s;
    __syncthreads();
    for (int st = 128; st > 0; st >>= 1) {
        if (tid < st) red[tid] += red[tid + st];
        __syncthreads();
    }
    if (tid == 0) g_sum[b] = red[0];
}

// ---------------- K5: attn = softmax(S) @ bottom  ([HW x C]) ----------------
__global__ void k_gemm_attn()
{
    const int b  = blockIdx.z;
    const int n0 = blockIdx.x * 128;   // over C=256
    const int m0 = blockIdx.y * 128;   // over HW
    const int t  = threadIdx.x;
    const int tx = t & 15, ty = t >> 4;

    const float* A  = g_S + (size_t)b * HWS * HWS + (size_t)m0 * HWS;
    const float* Bm = g_bottom + (size_t)b * HWS * CC + n0;

    __shared__ float As[8][128];
    __shared__ float Bs[8][128];

    u64 acc2[8][4];
#pragma unroll
    for (int i = 0; i < 8; i++)
#pragma unroll
        for (int j = 0; j < 4; j++) acc2[i][j] = 0ULL;

    for (int k0 = 0; k0 < HWS; k0 += 8) {
        {
            int m  = t >> 1;
            int kq = (t & 1) * 4;
            float4 v = *(const float4*)(A + (size_t)m * HWS + k0 + kq);
            As[kq + 0][m] = __expf(v.x - 40.f);
            As[kq + 1][m] = __expf(v.y - 40.f);
            As[kq + 2][m] = __expf(v.z - 40.f);
            As[kq + 3][m] = __expf(v.w - 40.f);
        }
        {
            int kb = t >> 5;
            int nb = (t & 31) * 4;
            *(float4*)&Bs[kb][nb] = *(const float4*)(Bm + (size_t)(k0 + kb) * CC + nb);
        }
        __syncthreads();
#pragma unroll
        for (int kk = 0; kk < 8; kk++)
            mk_update(acc2, &As[kk][ty * 8], &Bs[kk][tx * 8]);
        __syncthreads();
    }

    const float inv = 1.0f / g_sum[b];
    float* outp = g_attn + (size_t)b * HWS * CC;
#pragma unroll
    for (int i = 0; i < 8; i++) {
        float2 f0 = unpack2(acc2[i][0]);
        float2 f1 = unpack2(acc2[i][1]);
        float2 f2 = unpack2(acc2[i][2]);
        float2 f3 = unpack2(acc2[i][3]);
        float* row = outp + (size_t)(m0 + ty * 8 + i) * CC + n0 + tx * 8;
        *(float4*)(row)     = make_float4(f0.x * inv, f0.y * inv, f1.x * inv, f1.y * inv);
        *(float4*)(row + 4) = make_float4(f2.x * inv, f2.y * inv, f3.x * inv, f3.y * inv);
    }
}

// ---------------- K6: out = conv3x3(x + attn_reinterp, w_out) + b_out -------
__global__ void k_conv_out(const float* __restrict__ x,
                           const float* __restrict__ w, const float* __restrict__ bias,
                           float* __restrict__ out)
{
    const int b  = blockIdx.z;
    const int n0 = blockIdx.x * 128;
    const int m0 = blockIdx.y * 128;
    const int t  = threadIdx.x;
    const int tx = t & 15, ty = t >> 4;

    __shared__ float As[8][128];
    __shared__ float Bs[8][128];

    u64 acc2[8][4];
#pragma unroll
    for (int i = 0; i < 8; i++)
#pragma unroll
        for (int j = 0; j < 4; j++) acc2[i][j] = 0ULL;

    const float* xb = x + (size_t)b * CC * HWS;
    const float* zb = g_attn + (size_t)b * HWS * CC;   // reinterpreted [C][H][W]

    for (int k0 = 0; k0 < 2304; k0 += 8) {
        {
            int m  = t >> 1;
            int kq = (t & 1) * 4;
            float4 v = *(const float4*)(w + (size_t)(m0 + m) * 2304 + k0 + kq);
            As[kq + 0][m] = v.x; As[kq + 1][m] = v.y; As[kq + 2][m] = v.z; As[kq + 3][m] = v.w;
        }
        {
            int kb   = t >> 5;
            int kidx = k0 + kb;
            int ci   = kidx / 9;
            int r    = kidx - ci * 9;
            int dh   = r / 3 - 1;
            int dw   = r - (r / 3) * 3 - 1;
            const float* srcx = xb + (size_t)ci * HWS;
            const float* srcz = zb + (size_t)ci * HWS;
            int lane = t & 31;
#pragma unroll
            for (int it = 0; it < 4; it++) {
                int n  = n0 + lane + 32 * it;
                int h  = n >> 6, wc_ = n & 63;
                int hh = h + dh, ww = wc_ + dw;
                float v = 0.f;
                if ((unsigned)hh < 64u && (unsigned)ww < 64u) {
                    int off = hh * 64 + ww;
                    v = srcx[off] + srcz[off];
                }
                Bs[kb][lane + 32 * it] = v;
            }
        }
        __syncthreads();
#pragma unroll
        for (int kk = 0; kk < 8; kk++)
            mk_update(acc2, &As[kk][ty * 8], &Bs[kk][tx * 8]);
        __syncthreads();
    }

#pragma unroll
    for (int i = 0; i < 8; i++) {
        int co = m0 + ty * 8 + i;
        float bv = bias[co];
        float2 f0 = unpack2(acc2[i][0]);
        float2 f1 = unpack2(acc2[i][1]);
        float2 f2 = unpack2(acc2[i][2]);
        float2 f3 = unpack2(acc2[i][3]);
        float* row = out + (size_t)b * CC * HWS + (size_t)co * HWS + n0 + tx * 8;
        *(float4*)(row)     = make_float4(f0.x + bv, f0.y + bv, f1.x + bv, f1.y + bv);
        *(float4*)(row + 4) = make_float4(f2.x + bv, f2.y + bv, f3.x + bv, f3.y + bv);
    }
}

// ---------------- launch ----------------------------------------------------
extern "C" void kernel_launch(void* const* d_in, const int* in_sizes, int n_in,
                              void* d_out, int out_size)
{
    const float* x  = (const float*)d_in[0];
    const float* wt = (const float*)d_in[1];
    const float* bt = (const float*)d_in[2];
    const float* wc = (const float*)d_in[3];
    const float* bc = (const float*)d_in[4];
    const float* wb = (const float*)d_in[5];
    const float* bbm = (const float*)d_in[6];
    const float* wo = (const float*)d_in[7];
    const float* bo = (const float*)d_in[8];
    float* out = (float*)d_out;

    k_top_center<<<dim3(HWS / 64, BB), 256>>>(x, wt, bt, wc, bc);
    k_conv_bottom<<<dim3(HWS / 128, CC / 128, BB), 256>>>(x, wb, bbm);
    k_gemm_S<<<dim3(HWS / 128, HWS / 128, BB), 256>>>();
    k_expsum<<<dim3(2048, BB), 256>>>();
    k_expsum2<<<BB, 256>>>();
    k_gemm_attn<<<dim3(CC / 128, HWS / 128, BB), 256>>>();
    k_conv_out<<<dim3(HWS / 128, CC / 128, BB), 256>>>(x, wo, bo, out);
}

// round 6
// speedup vs baseline: 2.0766x; 2.0766x over previous
#include <cuda_runtime.h>
#include <cstdint>

#define BB  8
#define CC  256
#define PP  64
#define HWS 4096

// ---------------- scratch (device globals) ----------------------------------
__device__ __align__(128) float g_topT[BB * HWS * PP];      // [B][HW][P]
__device__ __align__(128) float g_centerT[BB * HWS * PP];   // [B][HW][P]
__device__ __align__(128) float g_bottomT[BB * CC * HWS];   // [B][C][HW]
__device__ __align__(128) float g_S[134217728];             // [B][HW][HW]; holds E=exp(S-40)
__device__ __align__(128) float g_attn[BB * HWS * CC];      // [B][HW][C]
__device__ float g_partialS[BB * 1024];
__device__ float g_sum[BB];

// ---------------- tf32 helpers ----------------------------------------------
__device__ __forceinline__ float tf32r(float x) {
    uint32_t u;
    asm("cvt.rna.tf32.f32 %0, %1;" : "=r"(u) : "f"(x));
    return __uint_as_float(u);
}

__device__ __forceinline__ void mma8(float* d, const uint32_t* a, const uint32_t* b) {
    asm volatile(
        "mma.sync.aligned.m16n8k8.row.col.f32.tf32.tf32.f32 "
        "{%0,%1,%2,%3}, {%4,%5,%6,%7}, {%8,%9}, {%0,%1,%2,%3};"
        : "+f"(d[0]), "+f"(d[1]), "+f"(d[2]), "+f"(d[3])
        : "r"(a[0]), "r"(a[1]), "r"(a[2]), "r"(a[3]), "r"(b[0]), "r"(b[1]));
}

// SW128-equivalent swizzle on a [128 rows][32 floats] panel.
// float index for (row r, col k): chunk (k>>2) XOR (r&7).
__device__ __forceinline__ int swidx(int r, int k) {
    return r * 32 + (((k >> 2) ^ (r & 7)) << 2) + (k & 3);
}

// ---------------- panel loaders (256 threads, panel = 128 x 32) --------------
// generic K-major: row r from src + r*lda + k0
__device__ __forceinline__ void load_panel(float* pan, const float* src, int lda, int k0) {
    int r  = threadIdx.x >> 1;
    int kq = (threadIdx.x & 1) * 4;
    const float* row = src + (size_t)r * lda + k0 + kq * 4;
#pragma unroll
    for (int j = 0; j < 4; j++) {
        float4 v = ((const float4*)row)[j];
        v.x = tf32r(v.x); v.y = tf32r(v.y); v.z = tf32r(v.z); v.w = tf32r(v.w);
        *(float4*)&pan[r * 32 + (((kq + j) ^ (r & 7)) << 2)] = v;
    }
}

// hi/lo split loader (for S)
__device__ __forceinline__ void load_panel_split(float* ph, float* pl,
                                                 const float* src, int lda, int k0) {
    int r  = threadIdx.x >> 1;
    int kq = (threadIdx.x & 1) * 4;
    const float* row = src + (size_t)r * lda + k0 + kq * 4;
#pragma unroll
    for (int j = 0; j < 4; j++) {
        float4 v = ((const float4*)row)[j];
        float4 h, l;
        h.x = tf32r(v.x); l.x = tf32r(v.x - h.x);
        h.y = tf32r(v.y); l.y = tf32r(v.y - h.y);
        h.z = tf32r(v.z); l.z = tf32r(v.z - h.z);
        h.w = tf32r(v.w); l.w = tf32r(v.w - h.w);
        int o = r * 32 + (((kq + j) ^ (r & 7)) << 2);
        *(float4*)&ph[o] = h;
        *(float4*)&pl[o] = l;
    }
}

// im2col loader: row = spatial n (n0+r), k = ci*9 + r3
template<bool ADDZ>
__device__ __forceinline__ void load_panel_im2col(float* pan, const float* xb,
                                                  const float* zb, int n0, int k0) {
    int r  = threadIdx.x >> 1;
    int kq = (threadIdx.x & 1) * 4;
    int n  = n0 + r;
    int h  = n >> 6, w = n & 63;
#pragma unroll
    for (int j = 0; j < 4; j++) {
        float vals[4];
#pragma unroll
        for (int e = 0; e < 4; e++) {
            int k  = k0 + (kq + j) * 4 + e;
            int ci = k / 9;
            int rr = k - ci * 9;
            int dh = rr / 3 - 1;
            int dw = rr - (rr / 3) * 3 - 1;
            int hh = h + dh, ww = w + dw;
            float v = 0.f;
            if ((unsigned)hh < 64u && (unsigned)ww < 64u) {
                int off = ci * HWS + hh * 64 + ww;
                v = xb[off];
                if (ADDZ) v += zb[off];
            }
            vals[e] = tf32r(v);
        }
        *(float4*)&pan[r * 32 + (((kq + j) ^ (r & 7)) << 2)] =
            make_float4(vals[0], vals[1], vals[2], vals[3]);
    }
}

// ---------------- warp compute over one k32 panel ----------------------------
// warp tile 64x32 at (warp_m, warp_n); acc[mi][ni][4]
__device__ __forceinline__ void panel_mma(float acc[4][4][4],
                                          const float* As, const float* Bs,
                                          int warp_m, int warp_n, int lane) {
    const uint32_t* Au = (const uint32_t*)As;
    const uint32_t* Bu = (const uint32_t*)Bs;
    int g = lane >> 2, t = lane & 3;
#pragma unroll
    for (int ks = 0; ks < 4; ks++) {
        int k = ks * 8;
        uint32_t af[4][4], bf[4][2];
#pragma unroll
        for (int mi = 0; mi < 4; mi++) {
            int mb = warp_m + mi * 16;
            af[mi][0] = Au[swidx(mb + g,     k + t)];
            af[mi][1] = Au[swidx(mb + g + 8, k + t)];
            af[mi][2] = Au[swidx(mb + g,     k + t + 4)];
            af[mi][3] = Au[swidx(mb + g + 8, k + t + 4)];
        }
#pragma unroll
        for (int ni = 0; ni < 4; ni++) {
            int nb = warp_n + ni * 8;
            bf[ni][0] = Bu[swidx(nb + g, k + t)];
            bf[ni][1] = Bu[swidx(nb + g, k + t + 4)];
        }
#pragma unroll
        for (int mi = 0; mi < 4; mi++)
#pragma unroll
            for (int ni = 0; ni < 4; ni++)
                mma8(acc[mi][ni], af[mi], bf[ni]);
    }
}

// ---------------- K1: 1x1 convs -> topT + centerT [B][HW][P] ----------------
__global__ void k_top_center(const float* __restrict__ x,
                             const float* __restrict__ wt, const float* __restrict__ bt,
                             const float* __restrict__ wc, const float* __restrict__ bc)
{
    const int b  = blockIdx.y;
    const int n0 = blockIdx.x * 64;
    const int t  = threadIdx.x;
    const int p  = t & 63;
    const int q  = t >> 6;

    __shared__ float xs[16][64];
    __shared__ float wts[64][17];
    __shared__ float wcs[64][17];

    float acct[16], accc[16];
#pragma unroll
    for (int j = 0; j < 16; j++) { acct[j] = 0.f; accc[j] = 0.f; }

    const float* xb = x + (size_t)b * CC * HWS;

    for (int c0 = 0; c0 < CC; c0 += 16) {
        {
            int cc = t >> 4;
            int nn = (t & 15) * 4;
            float4 v = *(const float4*)(xb + (size_t)(c0 + cc) * HWS + n0 + nn);
            *(float4*)&xs[cc][nn] = v;
        }
        {
            int p_ = t >> 2;
            int cq = (t & 3) * 4;
            float4 v = *(const float4*)(wt + (size_t)p_ * CC + c0 + cq);
            wts[p_][cq + 0] = v.x; wts[p_][cq + 1] = v.y; wts[p_][cq + 2] = v.z; wts[p_][cq + 3] = v.w;
            float4 u = *(const float4*)(wc + (size_t)p_ * CC + c0 + cq);
            wcs[p_][cq + 0] = u.x; wcs[p_][cq + 1] = u.y; wcs[p_][cq + 2] = u.z; wcs[p_][cq + 3] = u.w;
        }
        __syncthreads();
#pragma unroll
        for (int cc = 0; cc < 16; cc++) {
            float at = wts[p][cc];
            float ac = wcs[p][cc];
#pragma unroll
            for (int j = 0; j < 16; j++) {
                float xv = xs[cc][q * 16 + j];
                acct[j] += at * xv;
                accc[j] += ac * xv;
            }
        }
        __syncthreads();
    }

    const float btv = bt[p];
    const float bcv = bc[p];
    float* tp = g_topT    + (size_t)b * HWS * PP + (size_t)(n0 + q * 16) * PP + p;
    float* cp = g_centerT + (size_t)b * HWS * PP + (size_t)(n0 + q * 16) * PP + p;
#pragma unroll
    for (int j = 0; j < 16; j++) {
        tp[(size_t)j * PP] = acct[j] + btv;
        cp[(size_t)j * PP] = accc[j] + bcv;
    }
}

// ---------------- conv 3x3 as tf32 implicit GEMM (both convs) ----------------
template<bool ADDZ>
__global__ void __launch_bounds__(256, 2)
k_conv_t(const float* __restrict__ xin, const float* __restrict__ wgt,
         const float* __restrict__ bias, float* __restrict__ outp)
{
    __shared__ float As[4096];
    __shared__ float Bs[4096];

    const int b   = blockIdx.z;
    const int n0  = blockIdx.x * 128;
    const int m0  = blockIdx.y * 128;
    const int tid = threadIdx.x;
    const int wid = tid >> 5, lane = tid & 31;
    const int warp_m = (wid & 1) * 64;
    const int warp_n = (wid >> 1) * 32;

    const float* xb = xin + (size_t)b * CC * HWS;
    const float* zb = ADDZ ? (g_attn + (size_t)b * HWS * CC) : (const float*)0;
    const float* wrow = wgt + (size_t)m0 * 2304;

    float acc[4][4][4];
#pragma unroll
    for (int mi = 0; mi < 4; mi++)
#pragma unroll
        for (int ni = 0; ni < 4; ni++)
#pragma unroll
            for (int e = 0; e < 4; e++) acc[mi][ni][e] = 0.f;

    for (int c = 0; c < 72; c++) {
        __syncthreads();
        load_panel(As, wrow, 2304, c * 32);
        load_panel_im2col<ADDZ>(Bs, xb, zb, n0, c * 32);
        __syncthreads();
        panel_mma(acc, As, Bs, warp_m, warp_n, lane);
    }

    const int g = lane >> 2, t = lane & 3;
    float* obase;
    if (ADDZ) obase = outp + (size_t)b * CC * HWS;
    else      obase = g_bottomT + (size_t)b * CC * HWS;

#pragma unroll
    for (int mi = 0; mi < 4; mi++) {
        int m1 = m0 + warp_m + mi * 16 + g;
        int m2 = m1 + 8;
        float bv1 = bias[m1], bv2 = bias[m2];
#pragma unroll
        for (int ni = 0; ni < 4; ni++) {
            int n = n0 + warp_n + ni * 8 + 2 * t;
            *(float2*)(obase + (size_t)m1 * HWS + n) =
                make_float2(acc[mi][ni][0] + bv1, acc[mi][ni][1] + bv1);
            *(float2*)(obase + (size_t)m2 * HWS + n) =
                make_float2(acc[mi][ni][2] + bv2, acc[mi][ni][3] + bv2);
        }
    }
}

// ---------------- S = centerT @ topT^T (split tf32) + fused exp/sum ----------
__global__ void __launch_bounds__(256, 1) k_S_t()
{
    extern __shared__ float dyn[];
    float* Ah = dyn;
    float* Al = dyn + 4096;
    float* Bh = dyn + 8192;
    float* Bl = dyn + 12288;
    __shared__ float red[256];

    const int b   = blockIdx.z;
    const int n0  = blockIdx.x * 128;
    const int m0  = blockIdx.y * 128;
    const int tid = threadIdx.x;
    const int wid = tid >> 5, lane = tid & 31;
    const int warp_m = (wid & 1) * 64;
    const int warp_n = (wid >> 1) * 32;

    const float* A  = g_centerT + (size_t)b * HWS * PP + (size_t)m0 * PP;
    const float* Bt = g_topT    + (size_t)b * HWS * PP + (size_t)n0 * PP;

    float acc[4][4][4];
#pragma unroll
    for (int mi = 0; mi < 4; mi++)
#pragma unroll
        for (int ni = 0; ni < 4; ni++)
#pragma unroll
            for (int e = 0; e < 4; e++) acc[mi][ni][e] = 0.f;

    const uint32_t* Ahu = (const uint32_t*)Ah;
    const uint32_t* Alu = (const uint32_t*)Al;
    const uint32_t* Bhu = (const uint32_t*)Bh;
    const uint32_t* Blu = (const uint32_t*)Bl;
    const int g = lane >> 2, t = lane & 3;

    for (int c = 0; c < 2; c++) {
        __syncthreads();
        load_panel_split(Ah, Al, A,  PP, c * 32);
        load_panel_split(Bh, Bl, Bt, PP, c * 32);
        __syncthreads();
#pragma unroll
        for (int ks = 0; ks < 4; ks++) {
            int k = ks * 8;
            uint32_t ah[4][4], al[4][4], bh[4][2], bl[4][2];
#pragma unroll
            for (int mi = 0; mi < 4; mi++) {
                int mb = warp_m + mi * 16;
                ah[mi][0] = Ahu[swidx(mb + g,     k + t)];
                ah[mi][1] = Ahu[swidx(mb + g + 8, k + t)];
                ah[mi][2] = Ahu[swidx(mb + g,     k + t + 4)];
                ah[mi][3] = Ahu[swidx(mb + g + 8, k + t + 4)];
                al[mi][0] = Alu[swidx(mb + g,     k + t)];
                al[mi][1] = Alu[swidx(mb + g + 8, k + t)];
                al[mi][2] = Alu[swidx(mb + g,     k + t + 4)];
                al[mi][3] = Alu[swidx(mb + g + 8, k + t + 4)];
            }
#pragma unroll
            for (int ni = 0; ni < 4; ni++) {
                int nb = warp_n + ni * 8;
                bh[ni][0] = Bhu[swidx(nb + g, k + t)];
                bh[ni][1] = Bhu[swidx(nb + g, k + t + 4)];
                bl[ni][0] = Blu[swidx(nb + g, k + t)];
                bl[ni][1] = Blu[swidx(nb + g, k + t + 4)];
            }
#pragma unroll
            for (int mi = 0; mi < 4; mi++)
#pragma unroll
                for (int ni = 0; ni < 4; ni++) {
                    mma8(acc[mi][ni], ah[mi], bh[ni]);
                    mma8(acc[mi][ni], ah[mi], bl[ni]);
                    mma8(acc[mi][ni], al[mi], bh[ni]);
                }
        }
    }

    // epilogue: E = exp(S - 40), local sum, deterministic block reduce
    float* Eb = g_S + (size_t)b * HWS * HWS;
    float ls = 0.f;
#pragma unroll
    for (int mi = 0; mi < 4; mi++) {
        int m1 = m0 + warp_m + mi * 16 + g;
        int m2 = m1 + 8;
#pragma unroll
        for (int ni = 0; ni < 4; ni++) {
            int n = n0 + warp_n + ni * 8 + 2 * t;
            float e0 = __expf(acc[mi][ni][0] - 40.f);
            float e1 = __expf(acc[mi][ni][1] - 40.f);
            float e2 = __expf(acc[mi][ni][2] - 40.f);
            float e3 = __expf(acc[mi][ni][3] - 40.f);
            ls += (e0 + e1) + (e2 + e3);
            *(float2*)(Eb + (size_t)m1 * HWS + n) = make_float2(e0, e1);
            *(float2*)(Eb + (size_t)m2 * HWS + n) = make_float2(e2, e3);
        }
    }
    red[tid] = ls;
    __syncthreads();
    for (int st = 128; st > 0; st >>= 1) {
        if (tid < st) red[tid] += red[tid + st];
        __syncthreads();
    }
    if (tid == 0) g_partialS[b * 1024 + blockIdx.y * 32 + blockIdx.x] = red[0];
}

// ---------------- reduce partial sums ----------------------------------------
__global__ void k_sumreduce()
{
    const int b = blockIdx.x;
    const int tid = threadIdx.x;
    __shared__ float red[256];
    float s = 0.f;
    for (int i = tid; i < 1024; i += 256) s += g_partialS[b * 1024 + i];
    red[tid] = s;
    __syncthreads();
    for (int st = 128; st > 0; st >>= 1) {
        if (tid < st) red[tid] += red[tid + st];
        __syncthreads();
    }
    if (tid == 0) g_sum[b] = s = red[0];
}

// ---------------- attn = (E/sum) @ bottomT^T ---------------------------------
__global__ void __launch_bounds__(256, 2) k_attn_t()
{
    __shared__ float As[4096];
    __shared__ float Bs[4096];

    const int b   = blockIdx.z;
    const int cb  = blockIdx.x * 128;   // C tile
    const int m0  = blockIdx.y * 128;   // HW tile
    const int tid = threadIdx.x;
    const int wid = tid >> 5, lane = tid & 31;
    const int warp_m = (wid & 1) * 64;
    const int warp_n = (wid >> 1) * 32;

    const float* A  = g_S       + (size_t)b * HWS * HWS + (size_t)m0 * HWS;
    const float* Bt = g_bottomT + (size_t)b * CC * HWS + (size_t)cb * HWS;

    float acc[4][4][4];
#pragma unroll
    for (int mi = 0; mi < 4; mi++)
#pragma unroll
        for (int ni = 0; ni < 4; ni++)
#pragma unroll
            for (int e = 0; e < 4; e++) acc[mi][ni][e] = 0.f;

    for (int c = 0; c < 128; c++) {
        __syncthreads();
        load_panel(As, A,  HWS, c * 32);
        load_panel(Bs, Bt, HWS, c * 32);
        __syncthreads();
        panel_mma(acc, As, Bs, warp_m, warp_n, lane);
    }

    const int g = lane >> 2, t = lane & 3;
    const float inv = 1.0f / g_sum[b];
    float* obase = g_attn + (size_t)b * HWS * CC;

#pragma unroll
    for (int mi = 0; mi < 4; mi++) {
        int m1 = m0 + warp_m + mi * 16 + g;
        int m2 = m1 + 8;
#pragma unroll
        for (int ni = 0; ni < 4; ni++) {
            int n = cb + warp_n + ni * 8 + 2 * t;
            *(float2*)(obase + (size_t)m1 * CC + n) =
                make_float2(acc[mi][ni][0] * inv, acc[mi][ni][1] * inv);
            *(float2*)(obase + (size_t)m2 * CC + n) =
                make_float2(acc[mi][ni][2] * inv, acc[mi][ni][3] * inv);
        }
    }
}

// ---------------- launch -----------------------------------------------------
extern "C" void kernel_launch(void* const* d_in, const int* in_sizes, int n_in,
                              void* d_out, int out_size)
{
    const float* x   = (const float*)d_in[0];
    const float* wt  = (const float*)d_in[1];
    const float* bt  = (const float*)d_in[2];
    const float* wc  = (const float*)d_in[3];
    const float* bc  = (const float*)d_in[4];
    const float* wb  = (const float*)d_in[5];
    const float* bbm = (const float*)d_in[6];
    const float* wo  = (const float*)d_in[7];
    const float* bo  = (const float*)d_in[8];
    float* out = (float*)d_out;

    static int s_init = 0;
    if (!s_init) {
        cudaFuncSetAttribute(k_S_t, cudaFuncAttributeMaxDynamicSharedMemorySize, 65536);
        s_init = 1;
    }

    k_top_center<<<dim3(HWS / 64, BB), 256>>>(x, wt, bt, wc, bc);
    k_conv_t<false><<<dim3(32, 2, BB), 256>>>(x, wb, bbm, nullptr);
    k_S_t<<<dim3(32, 32, BB), 256, 65536>>>();
    k_sumreduce<<<BB, 256>>>();
    k_attn_t<<<dim3(2, 32, BB), 256>>>();
    k_conv_t<true><<<dim3(32, 2, BB), 256>>>(x, wo, bo, out);
}